// round 17
// baseline (speedup 1.0000x reference)
#include <cuda_runtime.h>
#include <stdint.h>
#include <math.h>

// CB:[B,L,3] f32, mask:[B,L] f32, Y:[B,M,3] f32, Yt:[B,M] i32, Ym:[B,M] i32
// out: Y_out[B,L,K,3] ++ Y_t_out[B,L,K] ++ Y_m_out[B,L,K] ++ D[B,L]  (all f32)

#define BB 8
#define LL 2048
#define MM 4096
#define KSEL 25
#define NT 256
#define NC 16            // atoms per thread; atom m = 4*tid + 1024*i + j
#define NWARP 8
#define CAP 1024         // candidate buffer capacity

typedef unsigned long long u64;
typedef unsigned int u32;

// atom index owned by this thread at local slot li (i = li>>2, j = li&3)
__device__ __forceinline__ int slot_m(int tid, int li) {
    return 4 * tid + ((li >> 2) << 10) + (li & 3);
}

// block-wide count of bits[] < T (strict). Uniform T, one barrier,
// double-buffered through `par`.
__device__ __forceinline__ int block_count(const u32* bits, u32 T,
                                           u32 (*wred)[NWARP], int& par,
                                           int warp, int lane)
{
    int c16 = 0;
    #pragma unroll
    for (int i = 0; i < NC; i++) c16 += (bits[i] < T) ? 1 : 0;
    u32 wc = __reduce_add_sync(0xffffffffu, (u32)c16);
    if (lane == 0) wred[par][warp] = wc;
    __syncthreads();
    int c = 0;
    #pragma unroll
    for (int w = 0; w < NWARP; w++) c += (int)wred[par][w];
    par ^= 1;
    return c;
}

__global__ __launch_bounds__(NT, 6)
void knn25_kernel(const float* __restrict__ CB,
                  const float* __restrict__ mask,
                  const float* __restrict__ Y,
                  const int*   __restrict__ Yt,
                  const int*   __restrict__ Ym,
                  float* __restrict__ out)
{
    __shared__ u64 cand[CAP];          // 8 KB
    __shared__ u64 res[KSEL];
    __shared__ u32 wred[2][NWARP];
    __shared__ int ncand;

    const int row  = blockIdx.x;       // b*LL + l
    const int b    = row >> 11;        // LL = 2048
    const int tid  = threadIdx.x;
    const int warp = tid >> 5;
    const int lane = tid & 31;

    const float* __restrict__ Yb  = Y  + (size_t)b * MM * 3;
    const int*   __restrict__ Ymb = Ym + b * MM;
    const int*   __restrict__ Ytb = Yt + b * MM;

    const size_t O1 = (size_t)BB * LL * KSEL * 3;
    const size_t O2 = O1 + (size_t)BB * LL * KSEL;
    const size_t O3 = O2 + (size_t)BB * LL * KSEL;

    // ---- Masked-row fast path (block-uniform, before any barrier) ----
    // mask==0 => all L2 = 1000 => top_k picks indices 0..24, D = sqrt(1000)
    if (mask[row] == 0.0f) {
        if (tid < KSEL) {
            const int m = tid;
            const size_t po = (size_t)row * KSEL + tid;
            out[po * 3 + 0] = Yb[m * 3 + 0];
            out[po * 3 + 1] = Yb[m * 3 + 1];
            out[po * 3 + 2] = Yb[m * 3 + 2];
            out[O1 + po]    = (float)Ytb[m];
            out[O2 + po]    = (float)Ymb[m];
            if (tid == 0) out[O3 + row] = sqrtf(1000.0f);
        }
        return;
    }

    const float cbx = CB[row * 3 + 0];
    const float cby = CB[row * 3 + 1];
    const float cbz = CB[row * 3 + 2];

    if (tid == 0) ncand = 0;

    // ---- Phase 1: vectorized distance pass (3x float4 + 1x int4 per 4 atoms)
    // ordering key = (d2_bits << 32) | m : monotone in d2, ties by smaller m
    const float4* __restrict__ Y4  = reinterpret_cast<const float4*>(Yb);
    const int4*   __restrict__ Ym4 = reinterpret_cast<const int4*>(Ymb);

    u32 bits[NC];
    u32 lmin = 0xFFFFFFFFu;
    #pragma unroll
    for (int i = 0; i < 4; i++) {
        const int q = tid + (i << 8);          // atoms 4q .. 4q+3
        const float4 f0 = Y4[3 * q + 0];       // x0 y0 z0 x1
        const float4 f1 = Y4[3 * q + 1];       // y1 z1 x2 y2
        const float4 f2 = Y4[3 * q + 2];       // z2 x3 y3 z3
        const int4   mq = Ym4[q];

        float dx, dy, dz, d2;

        dx = cbx - f0.x; dy = cby - f0.y; dz = cbz - f0.z;
        d2 = fmaf(dx, dx, fmaf(dy, dy, dz * dz));
        bits[i * 4 + 0] = __float_as_uint((mq.x != 0) ? d2 : 1000.0f);

        dx = cbx - f0.w; dy = cby - f1.x; dz = cbz - f1.y;
        d2 = fmaf(dx, dx, fmaf(dy, dy, dz * dz));
        bits[i * 4 + 1] = __float_as_uint((mq.y != 0) ? d2 : 1000.0f);

        dx = cbx - f1.z; dy = cby - f1.w; dz = cbz - f2.x;
        d2 = fmaf(dx, dx, fmaf(dy, dy, dz * dz));
        bits[i * 4 + 2] = __float_as_uint((mq.z != 0) ? d2 : 1000.0f);

        dx = cbx - f2.y; dy = cby - f2.z; dz = cbz - f2.w;
        d2 = fmaf(dx, dx, fmaf(dy, dy, dz * dz));
        bits[i * 4 + 3] = __float_as_uint((mq.w != 0) ? d2 : 1000.0f);

        lmin = umin(lmin, umin(umin(bits[i*4+0], bits[i*4+1]),
                               umin(bits[i*4+2], bits[i*4+3])));
    }

    // ---- Phase 2: block min of d2 bits (seed for threshold search) ----
    {
        u32 wm = __reduce_min_sync(0xffffffffu, lmin);
        if (lane == 0) wred[0][warp] = wm;
    }
    __syncthreads();
    u32 g = wred[0][0];
    #pragma unroll
    for (int w = 1; w < NWARP; w++) g = umin(g, wred[0][w]);

    // ---- Phase 3: find T with KSEL <= cnt(<T) <= CAP ----
    // geometric ascent: +2 exponent steps (x4) from the min
    int par = 1;
    u32 lo = g;                        // cnt(<g) == 0 < KSEL
    u32 T  = umin(g + (2u << 23), 0x7F800000u);
    int c;
    for (;;) {
        c = block_count(bits, T, wred, par, warp, lane);
        if (c >= KSEL) break;
        lo = T;
        T  = umin(T + (2u << 23), 0x7F800000u);
    }
    u32 hi = T;
    int c_hi = c;
    bool tie = false;
    while (c_hi > CAP) {               // rare: shrink bracket by bisection
        if (hi - lo <= 1u) { tie = true; break; }   // point mass at value `lo`
        u32 mid = lo + ((hi - lo) >> 1);
        c = block_count(bits, mid, wred, par, warp, lane);
        if (c < KSEL) lo = mid;
        else { hi = mid; c_hi = c; }
    }

    // ---- Phase 4: compact candidates into smem ----
    int Ctot;
    if (!tie) {
        #pragma unroll
        for (int li = 0; li < NC; li++) {
            if (bits[li] < hi) {
                int p = atomicAdd(&ncand, 1);
                cand[p] = ((u64)bits[li] << 32) | (u32)slot_m(tid, li);
            }
        }
        __syncthreads();
        Ctot = ncand;                  // == c_hi, in [KSEL, CAP]
    } else {
        // exact-tie fallback (degenerate inputs only; cold path):
        // top-25 = {bits < lo} ++ smallest-m elements with bits == lo.
        #pragma unroll
        for (int li = 0; li < NC; li++) {
            if (bits[li] < lo) {
                int p = atomicAdd(&ncand, 1);
                cand[p] = ((u64)bits[li] << 32) | (u32)slot_m(tid, li);
            }
        }
        __syncthreads();
        const int c_lo = ncand;        // < KSEL
        const int rem  = KSEL - c_lo;
        // rem rounds of global min-m over remaining tie elements (m unique)
        u32 tmask = 0;
        #pragma unroll
        for (int li = 0; li < NC; li++)
            if (bits[li] == lo) tmask |= (1u << li);
        for (int r = 0; r < rem; r++) {
            u32 best = 0xFFFFFFFFu; int bli = -1;
            u32 t = tmask;
            while (t) {
                const int li = __ffs(t) - 1; t &= t - 1;
                const u32 m = (u32)slot_m(tid, li);
                if (m < best) { best = m; bli = li; }
            }
            u32 wm = __reduce_min_sync(0xffffffffu, best);
            if (lane == 0) wred[par][warp] = wm;
            __syncthreads();
            u32 gm = wred[par][0];
            #pragma unroll
            for (int w = 1; w < NWARP; w++) gm = umin(gm, wred[par][w]);
            par ^= 1;
            if (best == gm && bli >= 0) tmask &= ~(1u << bli);
            if (tid == 0) cand[c_lo + r] = ((u64)lo << 32) | gm;
        }
        __syncthreads();
        Ctot = KSEL;
    }

    // ---- Phase 5: exact rank-select (keys distinct: m embedded) ----
    for (int t = tid; t < Ctot; t += NT) {
        const u64 k = cand[t];
        int rk = 0;
        for (int j = 0; j < Ctot; j++) rk += (cand[j] < k) ? 1 : 0;
        if (rk < KSEL) res[rk] = k;
    }
    __syncthreads();

    // ---- Phase 6: gather + store ----
    if (tid < KSEL) {
        const u64 kk = res[tid];
        const int   m  = (u32)kk;
        const float d2 = __uint_as_float((u32)(kk >> 32));

        const size_t po = (size_t)row * KSEL + tid;
        out[po * 3 + 0] = Yb[m * 3 + 0];
        out[po * 3 + 1] = Yb[m * 3 + 1];
        out[po * 3 + 2] = Yb[m * 3 + 2];
        out[O1 + po]    = (float)Ytb[m];
        out[O2 + po]    = (float)Ymb[m];
        if (tid == 0) out[O3 + row] = sqrtf(d2);
    }
}

extern "C" void kernel_launch(void* const* d_in, const int* in_sizes, int n_in,
                              void* d_out, int out_size)
{
    (void)in_sizes; (void)n_in; (void)out_size;
    const float* CB   = (const float*)d_in[0];
    const float* mask = (const float*)d_in[1];
    const float* Y    = (const float*)d_in[2];
    const int*   Yt   = (const int*)d_in[3];
    const int*   Ym   = (const int*)d_in[4];
    float* out = (float*)d_out;

    knn25_kernel<<<BB * LL, NT>>>(CB, mask, Y, Yt, Ym, out);
}